// round 11
// baseline (speedup 1.0000x reference)
#include <cuda_runtime.h>
#include <math.h>

// Problem constants
#define NB     64
#define TT     2048
#define FRAME  512
#define ENCC   256
#define HIDD   128
#define GATES  512
#define MROWS  (NB * TT)          // 131072

// ---------------- scratch (device globals; no allocation allowed) ----------------
__device__ float  g_encf[MROWS * ENCC];   // encoder output [m][e], later est in-place
__device__ float  g_xg  [MROWS * GATES];  // precomputed input gates (reused by both LSTMs)
__device__ float  g_x1  [MROWS * HIDD];   // LSTM1 hidden sequence
__device__ float  g_x2  [MROWS * HIDD];   // LSTM2 hidden sequence
__device__ double g_part[2048];           // reduction partials
__device__ float  g_mean, g_rstd;

// ---------------- f32x2 packed-FMA helpers ----------------
__device__ __forceinline__ void ffma2(unsigned long long& d, unsigned long long a, unsigned long long b) {
    asm("fma.rn.f32x2 %0, %1, %2, %0;" : "+l"(d) : "l"(a), "l"(b));
}
__device__ __forceinline__ unsigned long long pack2(float x, float y) {
    unsigned long long r; asm("mov.b64 %0, {%1, %2};" : "=l"(r) : "f"(x), "f"(y)); return r;
}
__device__ __forceinline__ float2 unpack2(unsigned long long v) {
    float2 f; asm("mov.b64 {%0, %1}, %2;" : "=f"(f.x), "=f"(f.y) : "l"(v)); return f;
}

__device__ __forceinline__ float sigmoid_f(float x) { return __fdividef(1.f, 1.f + __expf(-x)); }
__device__ __forceinline__ float tanh_f(float x) {
    float e = __expf(2.f * x);
    return 1.f - __fdividef(2.f, e + 1.f);
}
__device__ __forceinline__ float sigmoidf_(float x) { return __fdividef(1.f, 1.f + __expf(-x)); }

// ---------------- generic tiled fp32 GEMM: C = A @ B^T (+mode-specific fusion) ----------------
// B is always row-major weights [NC][K]. BM=BN=128, BK=16, 256 threads.
// Microtile per thread: rows {4q..4q+3} U {64+4q..64+4q+3}, cols {4p..} U {64+4p..}.
// A-reads: lane-contiguous float4 (conflict-free). B-reads: broadcast ulonglong2 pairs for FMA2.
#define BM 128
#define BN 128
#define BK 16

enum GemmMode { MODE_ENC = 0, MODE_XG1 = 1, MODE_XG2 = 2, MODE_MASK = 3, MODE_DEC = 4 };

template <int MODE, int K, int NC>
__global__ void __launch_bounds__(256) gemm_kernel(
    const float* __restrict__ A, const float* __restrict__ B, float* __restrict__ C,
    const float* __restrict__ bias1, const float* __restrict__ bias2,
    const float* __restrict__ gamma, const float* __restrict__ beta)
{
    __shared__ __align__(16) float As[BK][BM];
    __shared__ __align__(16) float Bs[BK][BN];

    const int tid = threadIdx.x;
    const int uq  = tid & 15;
    const int up  = tid >> 4;
    const int ra  = uq * 4, rb = 64 + uq * 4;
    const int ca  = up * 4, cb = 64 + up * 4;
    const int m0  = blockIdx.y * BM;
    const int j0  = blockIdx.x * BN;

    float mn = 0.f, rs = 0.f;
    if (MODE == MODE_XG1) { mn = g_mean; rs = g_rstd; }

    unsigned long long acc[8][4];
#pragma unroll
    for (int i = 0; i < 8; ++i)
#pragma unroll
        for (int j = 0; j < 4; ++j) acc[i][j] = 0ull;

    for (int k0 = 0; k0 < K; k0 += BK) {
        // ---- load A tile into As[k][m] ----
        if (MODE == MODE_ENC) {
            // A = y1 [NB][FRAME][TT]; row m=(n,t): a(m,k)=y1[n][k][t]; tiles never cross n
            const int n  = m0 >> 11;
            const int t0 = m0 & (TT - 1);
#pragma unroll
            for (int it = 0; it < 2; ++it) {
                int q  = tid + it * 256;
                int kk = q >> 5;
                int tv = (q & 31) * 4;
                const float4 v = *(const float4*)(A + ((size_t)(n * FRAME + k0 + kk)) * TT + t0 + tv);
                *(float4*)(&As[kk][tv]) = v;
            }
        } else {
            // A row-major [m][K]
#pragma unroll
            for (int it = 0; it < 2; ++it) {
                int q   = tid + it * 256;
                int row = q >> 2;
                int kv  = (q & 3) * 4;
                float4 v = *(const float4*)(A + (size_t)(m0 + row) * K + k0 + kv);
                if (MODE == MODE_XG1) {  // fuse global layernorm into A-read
                    v.x = (v.x - mn) * rs * gamma[k0 + kv + 0] + beta[k0 + kv + 0];
                    v.y = (v.y - mn) * rs * gamma[k0 + kv + 1] + beta[k0 + kv + 1];
                    v.z = (v.z - mn) * rs * gamma[k0 + kv + 2] + beta[k0 + kv + 2];
                    v.w = (v.w - mn) * rs * gamma[k0 + kv + 3] + beta[k0 + kv + 3];
                }
                As[kv + 0][row] = v.x; As[kv + 1][row] = v.y;
                As[kv + 2][row] = v.z; As[kv + 3][row] = v.w;
            }
        }
        // ---- load B tile (weights [NC][K]) into Bs[k][j] ----
#pragma unroll
        for (int it = 0; it < 2; ++it) {
            int q  = tid + it * 256;
            int jj = q >> 2;
            int kv = (q & 3) * 4;
            const float4 v = *(const float4*)(B + (size_t)(j0 + jj) * K + k0 + kv);
            Bs[kv + 0][jj] = v.x; Bs[kv + 1][jj] = v.y;
            Bs[kv + 2][jj] = v.z; Bs[kv + 3][jj] = v.w;
        }
        __syncthreads();
#pragma unroll
        for (int kk = 0; kk < BK; ++kk) {
            const float4 a0 = *(const float4*)(&As[kk][ra]);
            const float4 a1 = *(const float4*)(&As[kk][rb]);
            const ulonglong2 b0 = *(const ulonglong2*)(&Bs[kk][ca]);
            const ulonglong2 b1 = *(const ulonglong2*)(&Bs[kk][cb]);
            unsigned long long ad[8];
            ad[0] = pack2(a0.x, a0.x); ad[1] = pack2(a0.y, a0.y);
            ad[2] = pack2(a0.z, a0.z); ad[3] = pack2(a0.w, a0.w);
            ad[4] = pack2(a1.x, a1.x); ad[5] = pack2(a1.y, a1.y);
            ad[6] = pack2(a1.z, a1.z); ad[7] = pack2(a1.w, a1.w);
#pragma unroll
            for (int i = 0; i < 8; ++i) {
                ffma2(acc[i][0], ad[i], b0.x);
                ffma2(acc[i][1], ad[i], b0.y);
                ffma2(acc[i][2], ad[i], b1.x);
                ffma2(acc[i][3], ad[i], b1.y);
            }
        }
        __syncthreads();
    }

    // ---- unpack accumulators: c8[i][j], rows i: 0-3 -> ra+i, 4-7 -> rb+i-4; cols j: 0-3 -> ca+j, 4-7 -> cb+j-4
    float c8[8][8];
#pragma unroll
    for (int i = 0; i < 8; ++i) {
        float2 t0 = unpack2(acc[i][0]), t1 = unpack2(acc[i][1]);
        float2 t2 = unpack2(acc[i][2]), t3 = unpack2(acc[i][3]);
        c8[i][0] = t0.x; c8[i][1] = t0.y; c8[i][2] = t1.x; c8[i][3] = t1.y;
        c8[i][4] = t2.x; c8[i][5] = t2.y; c8[i][6] = t3.x; c8[i][7] = t3.y;
    }

    // ---- epilogue ----
    if (MODE == MODE_DEC) {
        // C = d_out [NB][FRAME][TT]; vectorize along t (thread's contiguous row groups)
        const int n   = m0 >> 11;
        const int t0a = (m0 & (TT - 1)) + ra;
        const int t0b = (m0 & (TT - 1)) + rb;
#pragma unroll
        for (int j = 0; j < 8; ++j) {
            const int col = j0 + ((j < 4) ? (ca + j) : (cb + j - 4));
            float* base = C + ((size_t)n * FRAME + col) * TT;
            *(float4*)(base + t0a) = make_float4(c8[0][j], c8[1][j], c8[2][j], c8[3][j]);
            *(float4*)(base + t0b) = make_float4(c8[4][j], c8[5][j], c8[6][j], c8[7][j]);
        }
    } else {
        float bj[8];
#pragma unroll
        for (int j = 0; j < 8; ++j) {
            const int col = j0 + ((j < 4) ? (ca + j) : (cb + j - 4));
            if (MODE == MODE_XG1 || MODE == MODE_XG2) bj[j] = bias1[col] + bias2[col];
            else if (MODE == MODE_MASK)               bj[j] = bias1[col];
            else                                      bj[j] = 0.f;
        }
#pragma unroll
        for (int i = 0; i < 8; ++i) {
            const int row = m0 + ((i < 4) ? (ra + i) : (rb + i - 4));
            float* p = C + (size_t)row * NC + j0;
            if (MODE == MODE_MASK) {
                // est = sigmoid(x2@Wd^T + bd) * encf  (in place into encf)
                float4 e0 = *(const float4*)(p + ca);
                float4 e1 = *(const float4*)(p + cb);
                float4 v0, v1;
                v0.x = sigmoidf_(c8[i][0] + bj[0]) * e0.x;
                v0.y = sigmoidf_(c8[i][1] + bj[1]) * e0.y;
                v0.z = sigmoidf_(c8[i][2] + bj[2]) * e0.z;
                v0.w = sigmoidf_(c8[i][3] + bj[3]) * e0.w;
                v1.x = sigmoidf_(c8[i][4] + bj[4]) * e1.x;
                v1.y = sigmoidf_(c8[i][5] + bj[5]) * e1.y;
                v1.z = sigmoidf_(c8[i][6] + bj[6]) * e1.z;
                v1.w = sigmoidf_(c8[i][7] + bj[7]) * e1.w;
                *(float4*)(p + ca) = v0;
                *(float4*)(p + cb) = v1;
            } else {
                *(float4*)(p + ca) = make_float4(c8[i][0] + bj[0], c8[i][1] + bj[1],
                                                 c8[i][2] + bj[2], c8[i][3] + bj[3]);
                *(float4*)(p + cb) = make_float4(c8[i][4] + bj[4], c8[i][5] + bj[5],
                                                 c8[i][6] + bj[6], c8[i][7] + bj[7]);
            }
        }
    }
}

// ---------------- deterministic global mean/var reduction ----------------
__global__ void reduce_kernel(const float* __restrict__ x, int n)
{
    __shared__ double sh[256];
    __shared__ double sh2[256];
    double s = 0.0, s2 = 0.0;
    for (int i = blockIdx.x * blockDim.x + threadIdx.x; i < n; i += gridDim.x * blockDim.x) {
        double v = (double)x[i];
        s += v; s2 += v * v;
    }
    sh[threadIdx.x] = s; sh2[threadIdx.x] = s2;
    __syncthreads();
    for (int off = 128; off > 0; off >>= 1) {
        if (threadIdx.x < off) {
            sh[threadIdx.x]  += sh[threadIdx.x + off];
            sh2[threadIdx.x] += sh2[threadIdx.x + off];
        }
        __syncthreads();
    }
    if (threadIdx.x == 0) {
        g_part[blockIdx.x]        = sh[0];
        g_part[1024 + blockIdx.x] = sh2[0];
    }
}

__global__ void finalize_kernel()
{
    __shared__ double sh[256];
    __shared__ double sh2[256];
    double s = 0.0, s2 = 0.0;
    for (int i = threadIdx.x; i < 1024; i += 256) { s += g_part[i]; s2 += g_part[1024 + i]; }
    sh[threadIdx.x] = s; sh2[threadIdx.x] = s2;
    __syncthreads();
    for (int off = 128; off > 0; off >>= 1) {
        if (threadIdx.x < off) {
            sh[threadIdx.x]  += sh[threadIdx.x + off];
            sh2[threadIdx.x] += sh2[threadIdx.x + off];
        }
        __syncthreads();
    }
    if (threadIdx.x == 0) {
        const double cnt  = (double)MROWS * (double)ENCC;
        const double mean = sh[0] / cnt;
        const double var  = sh2[0] / cnt - mean * mean;
        g_mean = (float)mean;
        g_rstd = (float)(1.0 / sqrt(var + 1e-7));
    }
}

// ---------------- persistent per-sample LSTM ----------------
// 64 blocks (1 per sample), 512 threads (1 per gate). f32x2 packed GEMV.
// Whh row split per gate: k[0,96) in 24 ulonglong2 REGISTERS (96 regs),
// k[96,128) in smem laid out wq[kq][gate] (contiguous per-warp -> conflict-free).
// Smem weight traffic: 64 KB/step (512 crossbar cyc) ~= FMA2 floor (512 cyc).
#define WREG 24   // ulonglong2 in registers  = 96 floats (k 0..95)
#define WSM  8    // ulonglong2 per thread in smem = 32 floats (k 96..127)
// smem: h_sh[128] + gates[512] + pad[16] -> 656 floats (2624 B, 16B aligned), then wq
#define LSTM_SMEM (656 * 4 + WSM * 512 * 16)

__global__ void __launch_bounds__(512, 1) lstm_kernel(
    const float* __restrict__ xg, const float* __restrict__ Whh,
    const float* __restrict__ states_in, float* __restrict__ states_out,
    float* __restrict__ xout, int slot_h, int slot_c)
{
    extern __shared__ __align__(16) float sm[];
    float*      h_sh  = sm;            // [128]
    float*      gates = sm + 128;      // [512]
    ulonglong2* wq    = (ulonglong2*)(sm + 656);  // [WSM][512]

    const int tid = threadIdx.x;
    const int n   = blockIdx.x;

    // load this gate's Whh row: 24 ulonglong2 to registers, 8 to smem
    const ulonglong2* wrow = (const ulonglong2*)(Whh + (size_t)tid * HIDD);
    ulonglong2 wreg[WREG];
#pragma unroll
    for (int i = 0; i < WREG; ++i) wreg[i] = wrow[i];
#pragma unroll
    for (int i = 0; i < WSM; ++i) wq[i * 512 + tid] = wrow[WREG + i];

    float c = 0.f;
    if (tid < HIDD) {
        h_sh[tid] = states_in[(size_t)slot_h * (NB * HIDD) + n * HIDD + tid];
        c         = states_in[(size_t)slot_c * (NB * HIDD) + n * HIDD + tid];
    }
    __syncthreads();

    const float* xg_n = xg   + (size_t)n * TT * GATES;
    float*       xo_n = xout + (size_t)n * TT * HIDD;

    float xval = xg_n[tid];   // prefetched input gate for t=0 (includes bih+bhh)
    for (int t = 0; t < TT; ++t) {
        // prefetch next step's input gate (hidden behind the GEMV)
        float xnext = (t + 1 < TT) ? xg_n[(size_t)(t + 1) * GATES + tid] : 0.f;

        const ulonglong2* h2 = (const ulonglong2*)h_sh;
        unsigned long long s0 = 0ull, s1 = 0ull, s2 = 0ull, s3 = 0ull;
#pragma unroll
        for (int i = 0; i < WREG; ++i) {
            const ulonglong2 h = h2[i];
            ffma2(s0, wreg[i].x, h.x);
            ffma2(s1, wreg[i].y, h.y);
        }
#pragma unroll
        for (int i = 0; i < WSM; ++i) {
            const ulonglong2 h = h2[WREG + i];
            const ulonglong2 w = wq[i * 512 + tid];
            ffma2(s2, w.x, h.x);
            ffma2(s3, w.y, h.y);
        }
        const float2 f0 = unpack2(s0), f1 = unpack2(s1), f2 = unpack2(s2), f3 = unpack2(s3);
        gates[tid] = xval + (((f0.x + f0.y) + (f1.x + f1.y)) + ((f2.x + f2.y) + (f3.x + f3.y)));
        __syncthreads();

        if (tid < HIDD) {  // units: i=tid, f=128+tid, g=256+tid, o=384+tid (PyTorch order)
            float iv = sigmoid_f(gates[tid]);
            float fv = sigmoid_f(gates[HIDD + tid]);
            float gv = tanh_f(gates[2 * HIDD + tid]);
            float ov = sigmoid_f(gates[3 * HIDD + tid]);
            c = fv * c + iv * gv;
            float h = ov * tanh_f(c);
            h_sh[tid] = h;
            xo_n[(size_t)t * HIDD + tid] = h;
        }
        __syncthreads();
        xval = xnext;
    }

    if (tid < HIDD) {
        states_out[(size_t)slot_h * (NB * HIDD) + n * HIDD + tid] = h_sh[tid];
        states_out[(size_t)slot_c * (NB * HIDD) + n * HIDD + tid] = c;
    }
}

// ---------------- launch ----------------
extern "C" void kernel_launch(void* const* d_in, const int* in_sizes, int n_in,
                              void* d_out, int out_size)
{
    const float* y1    = (const float*)d_in[0];
    const float* st_in = (const float*)d_in[1];
    const float* W_enc = (const float*)d_in[2];
    const float* gamma = (const float*)d_in[3];
    const float* beta  = (const float*)d_in[4];
    const float* Wih1  = (const float*)d_in[5];
    const float* Whh1  = (const float*)d_in[6];
    const float* bih1  = (const float*)d_in[7];
    const float* bhh1  = (const float*)d_in[8];
    const float* Wih2  = (const float*)d_in[9];
    const float* Whh2  = (const float*)d_in[10];
    const float* bih2  = (const float*)d_in[11];
    const float* bhh2  = (const float*)d_in[12];
    const float* Wd    = (const float*)d_in[13];
    const float* bd    = (const float*)d_in[14];
    const float* W_dec = (const float*)d_in[15];

    float* out        = (float*)d_out;
    float* states_out = out + ((size_t)out_size - 4 * NB * HIDD);

    float* encf; float* xg; float* x1; float* x2;
    cudaGetSymbolAddress((void**)&encf, g_encf);
    cudaGetSymbolAddress((void**)&xg,   g_xg);
    cudaGetSymbolAddress((void**)&x1,   g_x1);
    cudaGetSymbolAddress((void**)&x2,   g_x2);

    cudaFuncSetAttribute(lstm_kernel, cudaFuncAttributeMaxDynamicSharedMemorySize, LSTM_SMEM);

    const dim3 blk(256);
    const dim3 grid_enc (ENCC  / BN, MROWS / BM);
    const dim3 grid_g512(GATES / BN, MROWS / BM);
    const dim3 grid_mask(ENCC  / BN, MROWS / BM);

    // 1. encoder: encf[m][e] = sum_c W_enc[e,c] * y1[n,c,t]
    gemm_kernel<MODE_ENC, FRAME, ENCC><<<grid_enc, blk>>>(y1, W_enc, encf, 0, 0, 0, 0);
    // 2-3. global scalar mean/var (deterministic two-pass)
    reduce_kernel<<<1024, 256>>>(encf, MROWS * ENCC);
    finalize_kernel<<<1, 256>>>();
    // 4. xg1 = norm(encf) @ Wih1^T + (bih1+bhh1)   (layernorm fused into A-read)
    gemm_kernel<MODE_XG1, ENCC, GATES><<<grid_g512, blk>>>(encf, Wih1, xg, bih1, bhh1, gamma, beta);
    // 5. LSTM1 (slots 0/1) -> x1, states
    lstm_kernel<<<NB, 512, LSTM_SMEM>>>(xg, Whh1, st_in, states_out, x1, 0, 1);
    // 6. xg2 = x1 @ Wih2^T + (bih2+bhh2)
    gemm_kernel<MODE_XG2, HIDD, GATES><<<grid_g512, blk>>>(x1, Wih2, xg, bih2, bhh2, 0, 0);
    // 7. LSTM2 (slots 2/3) -> x2, states
    lstm_kernel<<<NB, 512, LSTM_SMEM>>>(xg, Whh2, st_in, states_out, x2, 2, 3);
    // 8. est = sigmoid(x2 @ Wd^T + bd) * encf   (in place into encf)
    gemm_kernel<MODE_MASK, HIDD, ENCC><<<grid_mask, blk>>>(x2, Wd, encf, bd, 0, 0, 0);
    // 9. decoded[n][f][t] = sum_e W_dec[f,e] * est[m][e]
    gemm_kernel<MODE_DEC, ENCC, FRAME><<<grid_g512, blk>>>(encf, W_dec, out, 0, 0, 0, 0);
}

// round 15
// speedup vs baseline: 1.4608x; 1.4608x over previous
#include <cuda_runtime.h>
#include <math.h>

// Problem constants
#define NB     64
#define TT     2048
#define FRAME  512
#define ENCC   256
#define HIDD   128
#define GATES  512
#define MROWS  (NB * TT)          // 131072

// ---------------- scratch (device globals; no allocation allowed) ----------------
__device__ float  g_encf[MROWS * ENCC];   // encoder output [m][e], later est in-place
__device__ float  g_xg  [MROWS * GATES];  // precomputed input gates (reused by both LSTMs)
__device__ float  g_x1  [MROWS * HIDD];   // LSTM1 hidden sequence
__device__ float  g_x2  [MROWS * HIDD];   // LSTM2 hidden sequence
__device__ double g_part[2048];           // reduction partials
__device__ float  g_mean, g_rstd;

// ---------------- f32x2 packed-FMA helpers (GEMM only) ----------------
__device__ __forceinline__ void ffma2(unsigned long long& d, unsigned long long a, unsigned long long b) {
    asm("fma.rn.f32x2 %0, %1, %2, %0;" : "+l"(d) : "l"(a), "l"(b));
}
__device__ __forceinline__ unsigned long long pack2(float x, float y) {
    unsigned long long r; asm("mov.b64 %0, {%1, %2};" : "=l"(r) : "f"(x), "f"(y)); return r;
}
__device__ __forceinline__ float2 unpack2(unsigned long long v) {
    float2 f; asm("mov.b64 {%0, %1}, %2;" : "=f"(f.x), "=f"(f.y) : "l"(v)); return f;
}

__device__ __forceinline__ float sigmoid_f(float x) { return __fdividef(1.f, 1.f + __expf(-x)); }
__device__ __forceinline__ float tanh_f(float x) {
    float e = __expf(2.f * x);
    return 1.f - __fdividef(2.f, e + 1.f);
}
__device__ __forceinline__ float sigmoidf_(float x) { return __fdividef(1.f, 1.f + __expf(-x)); }

// ---------------- generic tiled fp32 GEMM: C = A @ B^T (+mode-specific fusion) ----------------
// FMA2 inner product (ncu-verified ~2.3x FLOP rate vs scalar FFMA version)
#define BM 128
#define BN 128
#define BK 16

enum GemmMode { MODE_ENC = 0, MODE_XG1 = 1, MODE_XG2 = 2, MODE_MASK = 3, MODE_DEC = 4 };

template <int MODE, int K, int NC>
__global__ void __launch_bounds__(256) gemm_kernel(
    const float* __restrict__ A, const float* __restrict__ B, float* __restrict__ C,
    const float* __restrict__ bias1, const float* __restrict__ bias2,
    const float* __restrict__ gamma, const float* __restrict__ beta)
{
    __shared__ __align__(16) float As[BK][BM];
    __shared__ __align__(16) float Bs[BK][BN];

    const int tid = threadIdx.x;
    const int uq  = tid & 15;
    const int up  = tid >> 4;
    const int ra  = uq * 4, rb = 64 + uq * 4;
    const int ca  = up * 4, cb = 64 + up * 4;
    const int m0  = blockIdx.y * BM;
    const int j0  = blockIdx.x * BN;

    float mn = 0.f, rs = 0.f;
    if (MODE == MODE_XG1) { mn = g_mean; rs = g_rstd; }

    unsigned long long acc[8][4];
#pragma unroll
    for (int i = 0; i < 8; ++i)
#pragma unroll
        for (int j = 0; j < 4; ++j) acc[i][j] = 0ull;

    for (int k0 = 0; k0 < K; k0 += BK) {
        // ---- load A tile into As[k][m] ----
        if (MODE == MODE_ENC) {
            // A = y1 [NB][FRAME][TT]; row m=(n,t): a(m,k)=y1[n][k][t]; tiles never cross n
            const int n  = m0 >> 11;
            const int t0 = m0 & (TT - 1);
#pragma unroll
            for (int it = 0; it < 2; ++it) {
                int q  = tid + it * 256;
                int kk = q >> 5;
                int tv = (q & 31) * 4;
                const float4 v = *(const float4*)(A + ((size_t)(n * FRAME + k0 + kk)) * TT + t0 + tv);
                *(float4*)(&As[kk][tv]) = v;
            }
        } else {
            // A row-major [m][K]
#pragma unroll
            for (int it = 0; it < 2; ++it) {
                int q   = tid + it * 256;
                int row = q >> 2;
                int kv  = (q & 3) * 4;
                float4 v = *(const float4*)(A + (size_t)(m0 + row) * K + k0 + kv);
                if (MODE == MODE_XG1) {  // fuse global layernorm into A-read
                    v.x = (v.x - mn) * rs * gamma[k0 + kv + 0] + beta[k0 + kv + 0];
                    v.y = (v.y - mn) * rs * gamma[k0 + kv + 1] + beta[k0 + kv + 1];
                    v.z = (v.z - mn) * rs * gamma[k0 + kv + 2] + beta[k0 + kv + 2];
                    v.w = (v.w - mn) * rs * gamma[k0 + kv + 3] + beta[k0 + kv + 3];
                }
                As[kv + 0][row] = v.x; As[kv + 1][row] = v.y;
                As[kv + 2][row] = v.z; As[kv + 3][row] = v.w;
            }
        }
        // ---- load B tile (weights [NC][K]) into Bs[k][j] ----
#pragma unroll
        for (int it = 0; it < 2; ++it) {
            int q  = tid + it * 256;
            int jj = q >> 2;
            int kv = (q & 3) * 4;
            const float4 v = *(const float4*)(B + (size_t)(j0 + jj) * K + k0 + kv);
            Bs[kv + 0][jj] = v.x; Bs[kv + 1][jj] = v.y;
            Bs[kv + 2][jj] = v.z; Bs[kv + 3][jj] = v.w;
        }
        __syncthreads();
#pragma unroll
        for (int kk = 0; kk < BK; ++kk) {
            const float4 a0 = *(const float4*)(&As[kk][ra]);
            const float4 a1 = *(const float4*)(&As[kk][rb]);
            const ulonglong2 b0 = *(const ulonglong2*)(&Bs[kk][ca]);
            const ulonglong2 b1 = *(const ulonglong2*)(&Bs[kk][cb]);
            unsigned long long ad[8];
            ad[0] = pack2(a0.x, a0.x); ad[1] = pack2(a0.y, a0.y);
            ad[2] = pack2(a0.z, a0.z); ad[3] = pack2(a0.w, a0.w);
            ad[4] = pack2(a1.x, a1.x); ad[5] = pack2(a1.y, a1.y);
            ad[6] = pack2(a1.z, a1.z); ad[7] = pack2(a1.w, a1.w);
#pragma unroll
            for (int i = 0; i < 8; ++i) {
                ffma2(acc[i][0], ad[i], b0.x);
                ffma2(acc[i][1], ad[i], b0.y);
                ffma2(acc[i][2], ad[i], b1.x);
                ffma2(acc[i][3], ad[i], b1.y);
            }
        }
        __syncthreads();
    }

    // ---- unpack accumulators ----
    float c8[8][8];
#pragma unroll
    for (int i = 0; i < 8; ++i) {
        float2 t0 = unpack2(acc[i][0]), t1 = unpack2(acc[i][1]);
        float2 t2 = unpack2(acc[i][2]), t3 = unpack2(acc[i][3]);
        c8[i][0] = t0.x; c8[i][1] = t0.y; c8[i][2] = t1.x; c8[i][3] = t1.y;
        c8[i][4] = t2.x; c8[i][5] = t2.y; c8[i][6] = t3.x; c8[i][7] = t3.y;
    }

    // ---- epilogue ----
    if (MODE == MODE_DEC) {
        const int n   = m0 >> 11;
        const int t0a = (m0 & (TT - 1)) + ra;
        const int t0b = (m0 & (TT - 1)) + rb;
#pragma unroll
        for (int j = 0; j < 8; ++j) {
            const int col = j0 + ((j < 4) ? (ca + j) : (cb + j - 4));
            float* base = C + ((size_t)n * FRAME + col) * TT;
            *(float4*)(base + t0a) = make_float4(c8[0][j], c8[1][j], c8[2][j], c8[3][j]);
            *(float4*)(base + t0b) = make_float4(c8[4][j], c8[5][j], c8[6][j], c8[7][j]);
        }
    } else {
        float bj[8];
#pragma unroll
        for (int j = 0; j < 8; ++j) {
            const int col = j0 + ((j < 4) ? (ca + j) : (cb + j - 4));
            if (MODE == MODE_XG1 || MODE == MODE_XG2) bj[j] = bias1[col] + bias2[col];
            else if (MODE == MODE_MASK)               bj[j] = bias1[col];
            else                                      bj[j] = 0.f;
        }
#pragma unroll
        for (int i = 0; i < 8; ++i) {
            const int row = m0 + ((i < 4) ? (ra + i) : (rb + i - 4));
            float* p = C + (size_t)row * NC + j0;
            if (MODE == MODE_MASK) {
                float4 e0 = *(const float4*)(p + ca);
                float4 e1 = *(const float4*)(p + cb);
                float4 v0, v1;
                v0.x = sigmoidf_(c8[i][0] + bj[0]) * e0.x;
                v0.y = sigmoidf_(c8[i][1] + bj[1]) * e0.y;
                v0.z = sigmoidf_(c8[i][2] + bj[2]) * e0.z;
                v0.w = sigmoidf_(c8[i][3] + bj[3]) * e0.w;
                v1.x = sigmoidf_(c8[i][4] + bj[4]) * e1.x;
                v1.y = sigmoidf_(c8[i][5] + bj[5]) * e1.y;
                v1.z = sigmoidf_(c8[i][6] + bj[6]) * e1.z;
                v1.w = sigmoidf_(c8[i][7] + bj[7]) * e1.w;
                *(float4*)(p + ca) = v0;
                *(float4*)(p + cb) = v1;
            } else {
                *(float4*)(p + ca) = make_float4(c8[i][0] + bj[0], c8[i][1] + bj[1],
                                                 c8[i][2] + bj[2], c8[i][3] + bj[3]);
                *(float4*)(p + cb) = make_float4(c8[i][4] + bj[4], c8[i][5] + bj[5],
                                                 c8[i][6] + bj[6], c8[i][7] + bj[7]);
            }
        }
    }
}

// ---------------- deterministic global mean/var reduction ----------------
__global__ void reduce_kernel(const float* __restrict__ x, int n)
{
    __shared__ double sh[256];
    __shared__ double sh2[256];
    double s = 0.0, s2 = 0.0;
    for (int i = blockIdx.x * blockDim.x + threadIdx.x; i < n; i += gridDim.x * blockDim.x) {
        double v = (double)x[i];
        s += v; s2 += v * v;
    }
    sh[threadIdx.x] = s; sh2[threadIdx.x] = s2;
    __syncthreads();
    for (int off = 128; off > 0; off >>= 1) {
        if (threadIdx.x < off) {
            sh[threadIdx.x]  += sh[threadIdx.x + off];
            sh2[threadIdx.x] += sh2[threadIdx.x + off];
        }
        __syncthreads();
    }
    if (threadIdx.x == 0) {
        g_part[blockIdx.x]        = sh[0];
        g_part[1024 + blockIdx.x] = sh2[0];
    }
}

__global__ void finalize_kernel()
{
    __shared__ double sh[256];
    __shared__ double sh2[256];
    double s = 0.0, s2 = 0.0;
    for (int i = threadIdx.x; i < 1024; i += 256) { s += g_part[i]; s2 += g_part[1024 + i]; }
    sh[threadIdx.x] = s; sh2[threadIdx.x] = s2;
    __syncthreads();
    for (int off = 128; off > 0; off >>= 1) {
        if (threadIdx.x < off) {
            sh[threadIdx.x]  += sh[threadIdx.x + off];
            sh2[threadIdx.x] += sh2[threadIdx.x + off];
        }
        __syncthreads();
    }
    if (threadIdx.x == 0) {
        const double cnt  = (double)MROWS * (double)ENCC;
        const double mean = sh[0] / cnt;
        const double var  = sh2[0] / cnt - mean * mean;
        g_mean = (float)mean;
        g_rstd = (float)(1.0 / sqrt(var + 1e-7));
    }
}

// ---------------- persistent per-sample LSTM (R8 structure, rebalanced) ----------------
// 64 blocks (1 per sample), 512 threads (1 per gate). Plain FFMA, float4 weights
// (NO 64-bit register pairing -> no spills). Split per gate row:
//   k[0,72)   : 18 float4 in REGISTERS (~100 regs total, under the 128 cap)
//   k[72,128) : 14 float4 in smem, per-thread pitch 15 float4 (gcd(15,8)=1 -> conflict-free)
// Gate activations (sigmoid/tanh) applied by the 512 GEMV threads (warp-uniform branch),
// so the 128-thread serial tail is just c=f*c+i*g; h=o*tanh(c).
#define R4 18            // float4 weights in regs (72 floats)
#define S4 14            // float4 weights in smem (56 floats)
#define P4 15            // smem pitch in float4 per thread
// smem: h_sh[128] + gates[512] floats, then wsm[512][P4] float4
#define LSTM_SMEM (640 * 4 + 512 * P4 * 16)   // 2560 + 122880 = 125440 B

__global__ void __launch_bounds__(512, 1) lstm_kernel(
    const float* __restrict__ xg, const float* __restrict__ Whh,
    const float* __restrict__ states_in, float* __restrict__ states_out,
    float* __restrict__ xout, int slot_h, int slot_c)
{
    extern __shared__ __align__(16) float sm[];
    float*  h_sh  = sm;                        // [128]
    float*  gates = sm + 128;                  // [512] (activated)
    float4* wsm   = (float4*)(sm + 640);       // [512][P4]

    const int tid = threadIdx.x;
    const int n   = blockIdx.x;

    // load this gate's Whh row: 18 float4 to regs, 14 to smem
    const float4* wrow = (const float4*)(Whh + (size_t)tid * HIDD);
    float4 w[R4];
#pragma unroll
    for (int i = 0; i < R4; ++i) w[i] = wrow[i];
#pragma unroll
    for (int i = 0; i < S4; ++i) wsm[tid * P4 + i] = wrow[R4 + i];

    float c = 0.f;
    if (tid < HIDD) {
        h_sh[tid] = states_in[(size_t)slot_h * (NB * HIDD) + n * HIDD + tid];
        c         = states_in[(size_t)slot_c * (NB * HIDD) + n * HIDD + tid];
    }
    __syncthreads();

    const float* xg_n = xg   + (size_t)n * TT * GATES;
    float*       xo_n = xout + (size_t)n * TT * HIDD;
    const float4* wsr = wsm + tid * P4;
    const int gtype = tid >> 7;   // 0:i 1:f 2:g 3:o  (warp-uniform)

    float xval = xg_n[tid];   // prefetched input gate for t=0 (includes bih+bhh)
    for (int t = 0; t < TT; ++t) {
        // prefetch next step's input gate (hidden behind the GEMV)
        float xnext = (t + 1 < TT) ? xg_n[(size_t)(t + 1) * GATES + tid] : 0.f;

        const float4* h4 = (const float4*)h_sh;   // broadcast reads (N=1, ~free)
        float a0 = 0.f, a1 = 0.f, a2 = 0.f, a3 = 0.f;
#pragma unroll
        for (int i = 0; i < R4; ++i) {
            const float4 h = h4[i];
            a0 += w[i].x * h.x; a1 += w[i].y * h.y;
            a2 += w[i].z * h.z; a3 += w[i].w * h.w;
        }
#pragma unroll
        for (int i = 0; i < S4; ++i) {
            const float4 h = h4[R4 + i];
            const float4 ww = wsr[i];
            a0 += ww.x * h.x; a1 += ww.y * h.y;
            a2 += ww.z * h.z; a3 += ww.w * h.w;
        }
        const float gval = xval + ((a0 + a1) + (a2 + a3));
        // activation here (16 warps in parallel) instead of in the 4-warp tail
        gates[tid] = (gtype == 2) ? tanh_f(gval) : sigmoid_f(gval);
        __syncthreads();

        if (tid < HIDD) {
            const float iv = gates[tid];
            const float fv = gates[HIDD + tid];
            const float gv = gates[2 * HIDD + tid];
            const float ov = gates[3 * HIDD + tid];
            c = fv * c + iv * gv;
            const float h = ov * tanh_f(c);
            h_sh[tid] = h;
            xo_n[(size_t)t * HIDD + tid] = h;
        }
        __syncthreads();
        xval = xnext;
    }

    if (tid < HIDD) {
        states_out[(size_t)slot_h * (NB * HIDD) + n * HIDD + tid] = h_sh[tid];
        states_out[(size_t)slot_c * (NB * HIDD) + n * HIDD + tid] = c;
    }
}

// ---------------- launch ----------------
extern "C" void kernel_launch(void* const* d_in, const int* in_sizes, int n_in,
                              void* d_out, int out_size)
{
    const float* y1    = (const float*)d_in[0];
    const float* st_in = (const float*)d_in[1];
    const float* W_enc = (const float*)d_in[2];
    const float* gamma = (const float*)d_in[3];
    const float* beta  = (const float*)d_in[4];
    const float* Wih1  = (const float*)d_in[5];
    const float* Whh1  = (const float*)d_in[6];
    const float* bih1  = (const float*)d_in[7];
    const float* bhh1  = (const float*)d_in[8];
    const float* Wih2  = (const float*)d_in[9];
    const float* Whh2  = (const float*)d_in[10];
    const float* bih2  = (const float*)d_in[11];
    const float* bhh2  = (const float*)d_in[12];
    const float* Wd    = (const float*)d_in[13];
    const float* bd    = (const float*)d_in[14];
    const float* W_dec = (const float*)d_in[15];

    float* out        = (float*)d_out;
    float* states_out = out + ((size_t)out_size - 4 * NB * HIDD);

    float* encf; float* xg; float* x1; float* x2;
    cudaGetSymbolAddress((void**)&encf, g_encf);
    cudaGetSymbolAddress((void**)&xg,   g_xg);
    cudaGetSymbolAddress((void**)&x1,   g_x1);
    cudaGetSymbolAddress((void**)&x2,   g_x2);

    cudaFuncSetAttribute(lstm_kernel, cudaFuncAttributeMaxDynamicSharedMemorySize, LSTM_SMEM);

    const dim3 blk(256);
    const dim3 grid_enc (ENCC  / BN, MROWS / BM);
    const dim3 grid_g512(GATES / BN, MROWS / BM);
    const dim3 grid_mask(ENCC  / BN, MROWS / BM);

    // 1. encoder: encf[m][e] = sum_c W_enc[e,c] * y1[n,c,t]
    gemm_kernel<MODE_ENC, FRAME, ENCC><<<grid_enc, blk>>>(y1, W_enc, encf, 0, 0, 0, 0);
    // 2-3. global scalar mean/var (deterministic two-pass)
    reduce_kernel<<<1024, 256>>>(encf, MROWS * ENCC);
    finalize_kernel<<<1, 256>>>();
    // 4. xg1 = norm(encf) @ Wih1^T + (bih1+bhh1)   (layernorm fused into A-read)
    gemm_kernel<MODE_XG1, ENCC, GATES><<<grid_g512, blk>>>(encf, Wih1, xg, bih1, bhh1, gamma, beta);
    // 5. LSTM1 (slots 0/1) -> x1, states
    lstm_kernel<<<NB, 512, LSTM_SMEM>>>(xg, Whh1, st_in, states_out, x1, 0, 1);
    // 6. xg2 = x1 @ Wih2^T + (bih2+bhh2)
    gemm_kernel<MODE_XG2, HIDD, GATES><<<grid_g512, blk>>>(x1, Wih2, xg, bih2, bhh2, 0, 0);
    // 7. LSTM2 (slots 2/3) -> x2, states
    lstm_kernel<<<NB, 512, LSTM_SMEM>>>(xg, Whh2, st_in, states_out, x2, 2, 3);
    // 8. est = sigmoid(x2 @ Wd^T + bd) * encf   (in place into encf)
    gemm_kernel<MODE_MASK, HIDD, ENCC><<<grid_mask, blk>>>(x2, Wd, encf, bd, 0, 0, 0);
    // 9. decoded[n][f][t] = sum_e W_dec[f,e] * est[m][e]
    gemm_kernel<MODE_DEC, ENCC, FRAME><<<grid_g512, blk>>>(encf, W_dec, out, 0, 0, 0, 0);
}

// round 16
// speedup vs baseline: 1.5926x; 1.0902x over previous
#include <cuda_runtime.h>
#include <math.h>
#include <stdint.h>

// Problem constants
#define NB     64
#define TT     2048
#define FRAME  512
#define ENCC   256
#define HIDD   128
#define GATES  512
#define MROWS  (NB * TT)          // 131072

// ---------------- scratch (device globals; no allocation allowed) ----------------
__device__ float  g_encf[MROWS * ENCC];   // encoder output [m][e], later est in-place
__device__ float  g_xg  [MROWS * GATES];  // precomputed input gates (reused by both LSTMs)
__device__ float  g_x1  [MROWS * HIDD];   // LSTM1 hidden sequence
__device__ float  g_x2  [MROWS * HIDD];   // LSTM2 hidden sequence
__device__ double g_part[2048];           // reduction partials
__device__ float  g_mean, g_rstd;

// ---------------- f32x2 packed-FMA helpers ----------------
__device__ __forceinline__ void ffma2(unsigned long long& d, unsigned long long a, unsigned long long b) {
    asm("fma.rn.f32x2 %0, %1, %2, %0;" : "+l"(d) : "l"(a), "l"(b));
}
__device__ __forceinline__ unsigned long long pack2(float x, float y) {
    unsigned long long r; asm("mov.b64 %0, {%1, %2};" : "=l"(r) : "f"(x), "f"(y)); return r;
}
__device__ __forceinline__ float2 unpack2(unsigned long long v) {
    float2 f; asm("mov.b64 {%0, %1}, %2;" : "=f"(f.x), "=f"(f.y) : "l"(v)); return f;
}

__device__ __forceinline__ float sigmoid_f(float x) { return __fdividef(1.f, 1.f + __expf(-x)); }
__device__ __forceinline__ float tanh_f(float x) {
    float e = __expf(2.f * x);
    return 1.f - __fdividef(2.f, e + 1.f);
}
__device__ __forceinline__ float sigmoidf_(float x) { return __fdividef(1.f, 1.f + __expf(-x)); }

__device__ __forceinline__ uint32_t smem_u32(const void* p) {
    uint32_t a;
    asm("{ .reg .u64 t; cvta.to.shared.u64 t, %1; cvt.u32.u64 %0, t; }" : "=r"(a) : "l"(p));
    return a;
}

// ---------------- generic tiled fp32 GEMM: C = A @ B^T (+mode-specific fusion) ----------------
// FMA2 inner product (ncu-verified ~2.3x FLOP rate vs scalar FFMA version) — unchanged from R15
#define BM 128
#define BN 128
#define BK 16

enum GemmMode { MODE_ENC = 0, MODE_XG1 = 1, MODE_XG2 = 2, MODE_MASK = 3, MODE_DEC = 4 };

template <int MODE, int K, int NC>
__global__ void __launch_bounds__(256) gemm_kernel(
    const float* __restrict__ A, const float* __restrict__ B, float* __restrict__ C,
    const float* __restrict__ bias1, const float* __restrict__ bias2,
    const float* __restrict__ gamma, const float* __restrict__ beta)
{
    __shared__ __align__(16) float As[BK][BM];
    __shared__ __align__(16) float Bs[BK][BN];

    const int tid = threadIdx.x;
    const int uq  = tid & 15;
    const int up  = tid >> 4;
    const int ra  = uq * 4, rb = 64 + uq * 4;
    const int ca  = up * 4, cb = 64 + up * 4;
    const int m0  = blockIdx.y * BM;
    const int j0  = blockIdx.x * BN;

    float mn = 0.f, rs = 0.f;
    if (MODE == MODE_XG1) { mn = g_mean; rs = g_rstd; }

    unsigned long long acc[8][4];
#pragma unroll
    for (int i = 0; i < 8; ++i)
#pragma unroll
        for (int j = 0; j < 4; ++j) acc[i][j] = 0ull;

    for (int k0 = 0; k0 < K; k0 += BK) {
        // ---- load A tile into As[k][m] ----
        if (MODE == MODE_ENC) {
            const int n  = m0 >> 11;
            const int t0 = m0 & (TT - 1);
#pragma unroll
            for (int it = 0; it < 2; ++it) {
                int q  = tid + it * 256;
                int kk = q >> 5;
                int tv = (q & 31) * 4;
                const float4 v = *(const float4*)(A + ((size_t)(n * FRAME + k0 + kk)) * TT + t0 + tv);
                *(float4*)(&As[kk][tv]) = v;
            }
        } else {
#pragma unroll
            for (int it = 0; it < 2; ++it) {
                int q   = tid + it * 256;
                int row = q >> 2;
                int kv  = (q & 3) * 4;
                float4 v = *(const float4*)(A + (size_t)(m0 + row) * K + k0 + kv);
                if (MODE == MODE_XG1) {  // fuse global layernorm into A-read
                    v.x = (v.x - mn) * rs * gamma[k0 + kv + 0] + beta[k0 + kv + 0];
                    v.y = (v.y - mn) * rs * gamma[k0 + kv + 1] + beta[k0 + kv + 1];
                    v.z = (v.z - mn) * rs * gamma[k0 + kv + 2] + beta[k0 + kv + 2];
                    v.w = (v.w - mn) * rs * gamma[k0 + kv + 3] + beta[k0 + kv + 3];
                }
                As[kv + 0][row] = v.x; As[kv + 1][row] = v.y;
                As[kv + 2][row] = v.z; As[kv + 3][row] = v.w;
            }
        }
        // ---- load B tile (weights [NC][K]) into Bs[k][j] ----
#pragma unroll
        for (int it = 0; it < 2; ++it) {
            int q  = tid + it * 256;
            int jj = q >> 2;
            int kv = (q & 3) * 4;
            const float4 v = *(const float4*)(B + (size_t)(j0 + jj) * K + k0 + kv);
            Bs[kv + 0][jj] = v.x; Bs[kv + 1][jj] = v.y;
            Bs[kv + 2][jj] = v.z; Bs[kv + 3][jj] = v.w;
        }
        __syncthreads();
#pragma unroll
        for (int kk = 0; kk < BK; ++kk) {
            const float4 a0 = *(const float4*)(&As[kk][ra]);
            const float4 a1 = *(const float4*)(&As[kk][rb]);
            const ulonglong2 b0 = *(const ulonglong2*)(&Bs[kk][ca]);
            const ulonglong2 b1 = *(const ulonglong2*)(&Bs[kk][cb]);
            unsigned long long ad[8];
            ad[0] = pack2(a0.x, a0.x); ad[1] = pack2(a0.y, a0.y);
            ad[2] = pack2(a0.z, a0.z); ad[3] = pack2(a0.w, a0.w);
            ad[4] = pack2(a1.x, a1.x); ad[5] = pack2(a1.y, a1.y);
            ad[6] = pack2(a1.z, a1.z); ad[7] = pack2(a1.w, a1.w);
#pragma unroll
            for (int i = 0; i < 8; ++i) {
                ffma2(acc[i][0], ad[i], b0.x);
                ffma2(acc[i][1], ad[i], b0.y);
                ffma2(acc[i][2], ad[i], b1.x);
                ffma2(acc[i][3], ad[i], b1.y);
            }
        }
        __syncthreads();
    }

    // ---- unpack accumulators ----
    float c8[8][8];
#pragma unroll
    for (int i = 0; i < 8; ++i) {
        float2 t0 = unpack2(acc[i][0]), t1 = unpack2(acc[i][1]);
        float2 t2 = unpack2(acc[i][2]), t3 = unpack2(acc[i][3]);
        c8[i][0] = t0.x; c8[i][1] = t0.y; c8[i][2] = t1.x; c8[i][3] = t1.y;
        c8[i][4] = t2.x; c8[i][5] = t2.y; c8[i][6] = t3.x; c8[i][7] = t3.y;
    }

    // ---- epilogue ----
    if (MODE == MODE_DEC) {
        const int n   = m0 >> 11;
        const int t0a = (m0 & (TT - 1)) + ra;
        const int t0b = (m0 & (TT - 1)) + rb;
#pragma unroll
        for (int j = 0; j < 8; ++j) {
            const int col = j0 + ((j < 4) ? (ca + j) : (cb + j - 4));
            float* base = C + ((size_t)n * FRAME + col) * TT;
            *(float4*)(base + t0a) = make_float4(c8[0][j], c8[1][j], c8[2][j], c8[3][j]);
            *(float4*)(base + t0b) = make_float4(c8[4][j], c8[5][j], c8[6][j], c8[7][j]);
        }
    } else {
        float bj[8];
#pragma unroll
        for (int j = 0; j < 8; ++j) {
            const int col = j0 + ((j < 4) ? (ca + j) : (cb + j - 4));
            if (MODE == MODE_XG1 || MODE == MODE_XG2) bj[j] = bias1[col] + bias2[col];
            else if (MODE == MODE_MASK)               bj[j] = bias1[col];
            else                                      bj[j] = 0.f;
        }
#pragma unroll
        for (int i = 0; i < 8; ++i) {
            const int row = m0 + ((i < 4) ? (ra + i) : (rb + i - 4));
            float* p = C + (size_t)row * NC + j0;
            if (MODE == MODE_MASK) {
                float4 e0 = *(const float4*)(p + ca);
                float4 e1 = *(const float4*)(p + cb);
                float4 v0, v1;
                v0.x = sigmoidf_(c8[i][0] + bj[0]) * e0.x;
                v0.y = sigmoidf_(c8[i][1] + bj[1]) * e0.y;
                v0.z = sigmoidf_(c8[i][2] + bj[2]) * e0.z;
                v0.w = sigmoidf_(c8[i][3] + bj[3]) * e0.w;
                v1.x = sigmoidf_(c8[i][4] + bj[4]) * e1.x;
                v1.y = sigmoidf_(c8[i][5] + bj[5]) * e1.y;
                v1.z = sigmoidf_(c8[i][6] + bj[6]) * e1.z;
                v1.w = sigmoidf_(c8[i][7] + bj[7]) * e1.w;
                *(float4*)(p + ca) = v0;
                *(float4*)(p + cb) = v1;
            } else {
                *(float4*)(p + ca) = make_float4(c8[i][0] + bj[0], c8[i][1] + bj[1],
                                                 c8[i][2] + bj[2], c8[i][3] + bj[3]);
                *(float4*)(p + cb) = make_float4(c8[i][4] + bj[4], c8[i][5] + bj[5],
                                                 c8[i][6] + bj[6], c8[i][7] + bj[7]);
            }
        }
    }
}

// ---------------- deterministic global mean/var reduction ----------------
__global__ void reduce_kernel(const float* __restrict__ x, int n)
{
    __shared__ double sh[256];
    __shared__ double sh2[256];
    double s = 0.0, s2 = 0.0;
    for (int i = blockIdx.x * blockDim.x + threadIdx.x; i < n; i += gridDim.x * blockDim.x) {
        double v = (double)x[i];
        s += v; s2 += v * v;
    }
    sh[threadIdx.x] = s; sh2[threadIdx.x] = s2;
    __syncthreads();
    for (int off = 128; off > 0; off >>= 1) {
        if (threadIdx.x < off) {
            sh[threadIdx.x]  += sh[threadIdx.x + off];
            sh2[threadIdx.x] += sh2[threadIdx.x + off];
        }
        __syncthreads();
    }
    if (threadIdx.x == 0) {
        g_part[blockIdx.x]        = sh[0];
        g_part[1024 + blockIdx.x] = sh2[0];
    }
}

__global__ void finalize_kernel()
{
    __shared__ double sh[256];
    __shared__ double sh2[256];
    double s = 0.0, s2 = 0.0;
    for (int i = threadIdx.x; i < 1024; i += 256) { s += g_part[i]; s2 += g_part[1024 + i]; }
    sh[threadIdx.x] = s; sh2[threadIdx.x] = s2;
    __syncthreads();
    for (int off = 128; off > 0; off >>= 1) {
        if (threadIdx.x < off) {
            sh[threadIdx.x]  += sh[threadIdx.x + off];
            sh2[threadIdx.x] += sh2[threadIdx.x + off];
        }
        __syncthreads();
    }
    if (threadIdx.x == 0) {
        const double cnt  = (double)MROWS * (double)ENCC;
        const double mean = sh[0] / cnt;
        const double var  = sh2[0] / cnt - mean * mean;
        g_mean = (float)mean;
        g_rstd = (float)(1.0 / sqrt(var + 1e-7));
    }
}

// ---------------- persistent per-sample LSTM: 2-CTA cluster per sample ----------------
// grid = NB*2 CTAs, cluster (2,1,1), 256 threads/CTA, 1 gate per thread.
// rank0 owns gates i(0-127), f(128-255); rank1 owns g(256-383), o(384-511).
// All 128 Whh weights per gate in REGISTERS (32 ulonglong2, FMA2 GEMV; 255-reg cap
// at 256 threads -> no spills). Per step each CTA writes its 256 activated gates
// into the peer's smem (st.shared::cluster, double-buffered on t&1) and arrives on
// the peer's mbarrier (release.cluster, count=256); waits its own barrier with
// acquire.cluster parity t&1. Both CTAs redundantly compute c/h (no 2nd exchange).
__device__ __forceinline__ void mbar_wait_cluster(uint32_t mbar, uint32_t phase) {
    asm volatile(
        "{\n\t"
        ".reg .pred P1;\n\t"
        "WAIT_LOOP_%=:\n\t"
        "mbarrier.try_wait.parity.acquire.cluster.shared::cta.b64 P1, [%0], %1, 0x989680;\n\t"
        "@P1 bra.uni WAIT_DONE_%=;\n\t"
        "bra.uni WAIT_LOOP_%=;\n\t"
        "WAIT_DONE_%=:\n\t"
        "}"
        :: "r"(mbar), "r"(phase) : "memory");
}

__global__ void __launch_bounds__(256, 1) __cluster_dims__(2, 1, 1)
lstm_kernel(const float* __restrict__ xg, const float* __restrict__ Whh,
            const float* __restrict__ states_in, float* __restrict__ states_out,
            float* __restrict__ xout, int slot_h, int slot_c)
{
    __shared__ __align__(16) float h_sh[HIDD];
    __shared__ __align__(16) float allg[2][GATES];
    __shared__ __align__(8)  unsigned long long mbar[1];

    const int tid = threadIdx.x;
    const int n   = blockIdx.x >> 1;
    uint32_t rank;
    asm("mov.u32 %0, %%cluster_ctarank;" : "=r"(rank));
    const uint32_t peer = rank ^ 1u;
    const int g0   = (int)rank * 256;
    const int gidx = g0 + tid;

    const uint32_t mbar_a = smem_u32(mbar);
    const uint32_t allg_a = smem_u32(allg);
    uint32_t rem_mbar, rem_allg;
    asm("mapa.shared::cluster.u32 %0, %1, %2;" : "=r"(rem_mbar) : "r"(mbar_a), "r"(peer));
    asm("mapa.shared::cluster.u32 %0, %1, %2;" : "=r"(rem_allg) : "r"(allg_a), "r"(peer));

    if (tid == 0) {
        asm volatile("mbarrier.init.shared.b64 [%0], %1;" :: "r"(mbar_a), "r"(256u) : "memory");
    }

    // this gate's full Whh row in registers: 32 ulonglong2 = 128 floats
    const ulonglong2* wrow = (const ulonglong2*)(Whh + (size_t)gidx * HIDD);
    ulonglong2 w[32];
#pragma unroll
    for (int i = 0; i < 32; ++i) w[i] = wrow[i];

    float c = 0.f;
    if (tid < HIDD) {
        h_sh[tid] = states_in[(size_t)slot_h * (NB * HIDD) + n * HIDD + tid];
        c         = states_in[(size_t)slot_c * (NB * HIDD) + n * HIDD + tid];
    }
    // cluster sync: both CTAs' mbarrier init + h_sh visible before any exchange
    asm volatile("barrier.cluster.arrive.aligned;" ::: "memory");
    asm volatile("barrier.cluster.wait.aligned;"   ::: "memory");

    const float* xg_n = xg   + (size_t)n * TT * GATES;
    float*       xo_n = xout + (size_t)n * TT * HIDD;
    const bool   is_tanh = (rank == 1u) && (tid < HIDD);   // g-gate threads

    float xval = xg_n[gidx];   // prefetched input gate for t=0 (includes bih+bhh)
    for (int t = 0; t < TT; ++t) {
        float xnext = (t + 1 < TT) ? xg_n[(size_t)(t + 1) * GATES + gidx] : 0.f;

        // GEMV: 64 FMA2 over register weights, h broadcast from smem
        const ulonglong2* h2 = (const ulonglong2*)h_sh;
        unsigned long long s0 = 0ull, s1 = 0ull, s2 = 0ull, s3 = 0ull;
#pragma unroll
        for (int i = 0; i < 32; i += 2) {
            const ulonglong2 ha = h2[i];
            const ulonglong2 hb = h2[i + 1];
            ffma2(s0, w[i].x,     ha.x);
            ffma2(s1, w[i].y,     ha.y);
            ffma2(s2, w[i + 1].x, hb.x);
            ffma2(s3, w[i + 1].y, hb.y);
        }
        const float2 f0 = unpack2(s0), f1 = unpack2(s1), f2 = unpack2(s2), f3 = unpack2(s3);
        const float gval = xval + (((f0.x + f0.y) + (f1.x + f1.y)) + ((f2.x + f2.y) + (f3.x + f3.y)));
        const float act  = is_tanh ? tanh_f(gval) : sigmoid_f(gval);

        const int buf = t & 1;
        allg[buf][gidx] = act;                          // local copy
        {   // peer copy + signal (release orders the store before the arrive)
            const uint32_t raddr = rem_allg + (uint32_t)(buf * GATES + gidx) * 4u;
            asm volatile("st.shared::cluster.b32 [%0], %1;"
                         :: "r"(raddr), "r"(__float_as_uint(act)) : "memory");
            asm volatile("mbarrier.arrive.release.cluster.shared::cluster.b64 _, [%0];"
                         :: "r"(rem_mbar) : "memory");
        }
        mbar_wait_cluster(mbar_a, (uint32_t)(t & 1));   // peer's 256 gates arrived
        __syncthreads();                                // own-CTA gate stores visible

        if (tid < HIDD) {
            const float iv = allg[buf][tid];
            const float fv = allg[buf][HIDD + tid];
            const float gv = allg[buf][2 * HIDD + tid];
            const float ov = allg[buf][3 * HIDD + tid];
            c = fv * c + iv * gv;
            const float h = ov * tanh_f(c);
            h_sh[tid] = h;
            if (rank == 0u) xo_n[(size_t)t * HIDD + tid] = h;
        }
        __syncthreads();
        xval = xnext;
    }

    if (rank == 0u && tid < HIDD) {
        states_out[(size_t)slot_h * (NB * HIDD) + n * HIDD + tid] = h_sh[tid];
        states_out[(size_t)slot_c * (NB * HIDD) + n * HIDD + tid] = c;
    }
    // no CTA may exit while the peer could still write this CTA's smem
    asm volatile("barrier.cluster.arrive.aligned;" ::: "memory");
    asm volatile("barrier.cluster.wait.aligned;"   ::: "memory");
}

// ---------------- launch ----------------
extern "C" void kernel_launch(void* const* d_in, const int* in_sizes, int n_in,
                              void* d_out, int out_size)
{
    const float* y1    = (const float*)d_in[0];
    const float* st_in = (const float*)d_in[1];
    const float* W_enc = (const float*)d_in[2];
    const float* gamma = (const float*)d_in[3];
    const float* beta  = (const float*)d_in[4];
    const float* Wih1  = (const float*)d_in[5];
    const float* Whh1  = (const float*)d_in[6];
    const float* bih1  = (const float*)d_in[7];
    const float* bhh1  = (const float*)d_in[8];
    const float* Wih2  = (const float*)d_in[9];
    const float* Whh2  = (const float*)d_in[10];
    const float* bih2  = (const float*)d_in[11];
    const float* bhh2  = (const float*)d_in[12];
    const float* Wd    = (const float*)d_in[13];
    const float* bd    = (const float*)d_in[14];
    const float* W_dec = (const float*)d_in[15];

    float* out        = (float*)d_out;
    float* states_out = out + ((size_t)out_size - 4 * NB * HIDD);

    float* encf; float* xg; float* x1; float* x2;
    cudaGetSymbolAddress((void**)&encf, g_encf);
    cudaGetSymbolAddress((void**)&xg,   g_xg);
    cudaGetSymbolAddress((void**)&x1,   g_x1);
    cudaGetSymbolAddress((void**)&x2,   g_x2);

    const dim3 blk(256);
    const dim3 grid_enc (ENCC  / BN, MROWS / BM);
    const dim3 grid_g512(GATES / BN, MROWS / BM);
    const dim3 grid_mask(ENCC  / BN, MROWS / BM);

    // 1. encoder: encf[m][e] = sum_c W_enc[e,c] * y1[n,c,t]
    gemm_kernel<MODE_ENC, FRAME, ENCC><<<grid_enc, blk>>>(y1, W_enc, encf, 0, 0, 0, 0);
    // 2-3. global scalar mean/var (deterministic two-pass)
    reduce_kernel<<<1024, 256>>>(encf, MROWS * ENCC);
    finalize_kernel<<<1, 256>>>();
    // 4. xg1 = norm(encf) @ Wih1^T + (bih1+bhh1)   (layernorm fused into A-read)
    gemm_kernel<MODE_XG1, ENCC, GATES><<<grid_g512, blk>>>(encf, Wih1, xg, bih1, bhh1, gamma, beta);
    // 5. LSTM1 (slots 0/1) -> x1, states   (2 CTAs per sample, clustered)
    lstm_kernel<<<NB * 2, 256>>>(xg, Whh1, st_in, states_out, x1, 0, 1);
    // 6. xg2 = x1 @ Wih2^T + (bih2+bhh2)
    gemm_kernel<MODE_XG2, HIDD, GATES><<<grid_g512, blk>>>(x1, Wih2, xg, bih2, bhh2, 0, 0);
    // 7. LSTM2 (slots 2/3) -> x2, states
    lstm_kernel<<<NB * 2, 256>>>(xg, Whh2, st_in, states_out, x2, 2, 3);
    // 8. est = sigmoid(x2 @ Wd^T + bd) * encf   (in place into encf)
    gemm_kernel<MODE_MASK, HIDD, ENCC><<<grid_mask, blk>>>(x2, Wd, encf, bd, 0, 0, 0);
    // 9. decoded[n][f][t] = sum_e W_dec[f,e] * est[m][e]
    gemm_kernel<MODE_DEC, ENCC, FRAME><<<grid_g512, blk>>>(encf, W_dec, out, 0, 0, 0, 0);
}